// round 11
// baseline (speedup 1.0000x reference)
#include <cuda_runtime.h>

typedef unsigned long long ULL;
typedef unsigned int U32;

// ---------------- device scratch (no allocations allowed) ----------------
__device__ float g_UV[8 * 64 * 64 * 9 * 2];      // (u,v) per (b,h,w,n)
__device__ float g_Wt[1152 * 128];               // Wt[k][cout]
__device__ float g_xT[8 * 4096 * 128];           // NHWC transpose of x (16.8 MB)

// ---------------- packed f32x2 helpers ----------------
__device__ __forceinline__ ULL pack2(float lo, float hi) {
    ULL r; asm("mov.b64 %0, {%1,%2};" : "=l"(r) : "f"(lo), "f"(hi)); return r;
}
__device__ __forceinline__ void unpack2(ULL v, float& lo, float& hi) {
    asm("mov.b64 {%0,%1}, %2;" : "=f"(lo), "=f"(hi) : "l"(v));
}
__device__ __forceinline__ void fma2(ULL& d, ULL a, ULL b) {
    asm("fma.rn.f32x2 %0, %1, %2, %0;" : "+l"(d) : "l"(a), "l"(b));
}
__device__ __forceinline__ void cp_async16(U32 saddr, const void* gptr) {
    asm volatile("cp.async.ca.shared.global [%0], [%1], 16;\n"
                 :: "r"(saddr), "l"(gptr) : "memory");
}

// ============================================================================
// Fused prologue, LONG blocks FIRST:
//   [0, 128):      offset conv (128->18) + sampling-coord epilogue
//   [128, 704):    weight transpose  Wt[k][cout] = w_ker[cout][c][tap]
//   [704, 4800):   NCHW -> NHWC transpose of x
// ============================================================================
__global__ void __launch_bounds__(256) k_prep(const float* __restrict__ x,
                                              const float* __restrict__ w_off,
                                              const float* __restrict__ b_off,
                                              const float* __restrict__ w_ker) {
    __shared__ union {
        float tr[32][33];
        struct { float sx[8][324]; float sw[8][9][20]; } off;
    } sh;

    const int tid = threadIdx.x;
    const int bid = blockIdx.x;

    if (bid < 128) {
        // ---- offset conv, 16x16 pixel tile
        const int b  = bid >> 4;
        const int h0 = ((bid >> 2) & 3) * 16, w0 = (bid & 3) * 16;
        const int px = tid & 15, py = tid >> 4;

        ULL acc[10];
#pragma unroll
        for (int i = 0; i < 9; ++i) acc[i] = pack2(b_off[2 * i], b_off[2 * i + 1]);
        acc[9] = pack2(0.f, 0.f);

        for (int cc = 0; cc < 16; ++cc) {
            for (int e = tid; e < 8 * 324; e += 256) {
                int c = e / 324; int rem = e - c * 324;
                int r = rem / 18, col = rem - r * 18;
                int gh = h0 + r - 1, gw = w0 + col - 1;
                float v = 0.f;
                if (gh >= 0 && gh < 64 && gw >= 0 && gw < 64)
                    v = x[((b * 128 + cc * 8 + c) << 12) + (gh << 6) + gw];
                sh.off.sx[c][rem] = v;
            }
            for (int e = tid; e < 8 * 180; e += 256) {
                int c = e / 180; int rem = e - c * 180;
                int tap = rem / 20, o = rem - tap * 20;
                sh.off.sw[c][tap][o] =
                    (o < 18) ? w_off[(o * 128 + cc * 8 + c) * 9 + tap] : 0.f;
            }
            __syncthreads();

#pragma unroll
            for (int c = 0; c < 8; ++c) {
#pragma unroll
                for (int i = 0; i < 3; ++i) {
#pragma unroll
                    for (int j = 0; j < 3; ++j) {
                        float xv = sh.off.sx[c][(py + i) * 18 + (px + j)];
                        ULL xp = pack2(xv, xv);
                        const ulonglong2* wp = (const ulonglong2*)sh.off.sw[c][i * 3 + j];
                        ulonglong2 wA = wp[0], wB = wp[1], wC = wp[2], wD = wp[3], wE = wp[4];
                        fma2(acc[0], xp, wA.x); fma2(acc[1], xp, wA.y);
                        fma2(acc[2], xp, wB.x); fma2(acc[3], xp, wB.y);
                        fma2(acc[4], xp, wC.x); fma2(acc[5], xp, wC.y);
                        fma2(acc[6], xp, wD.x); fma2(acc[7], xp, wD.y);
                        fma2(acc[8], xp, wE.x); fma2(acc[9], xp, wE.y);
                    }
                }
            }
            __syncthreads();
        }

        float offs[18];
#pragma unroll
        for (int i = 0; i < 9; ++i) unpack2(acc[i], offs[2 * i], offs[2 * i + 1]);

        const int h = h0 + py, w = w0 + px;
        float2* uvp = (float2*)g_UV;
        const int basei = (b * 4096 + h * 64 + w) * 9;
#pragma unroll
        for (int n = 0; n < 9; ++n) {
            float u = (float)(h + n / 3 - 1) + offs[n];
            float v = (float)(w + n % 3 - 1) + offs[9 + n];
            u = fminf(fmaxf(u, 0.f), 63.f);
            v = fminf(fmaxf(v, 0.f), 63.f);
            uvp[basei + n] = make_float2(u, v);
        }
        return;
    }

    if (bid < 704) {
        // ---- weight transpose
        int i = (bid - 128) * 256 + tid;
        int o = i / 1152, k = i - o * 1152;
        g_Wt[k * 128 + o] = w_ker[i];
        return;
    }

    // ---- NCHW -> NHWC transpose
    {
        int rel = bid - 704;
        int s0 = (rel & 127) * 32;
        int c0 = ((rel >> 7) & 3) * 32;
        int b  = rel >> 9;
        int tx = tid & 31, ty = tid >> 5;   // (32, 8)
#pragma unroll
        for (int i = 0; i < 4; ++i) {
            int c = c0 + ty + i * 8;
            sh.tr[ty + i * 8][tx] = x[((b * 128 + c) << 12) + s0 + tx];
        }
        __syncthreads();
#pragma unroll
        for (int i = 0; i < 4; ++i) {
            int s = s0 + ty + i * 8;
            g_xT[(((b << 12) + s) << 7) + c0 + tx] = sh.tr[tx][ty + i * 8];
        }
    }
}

// ============================================================================
// Fused bilinear gather + GEMM.
//   Block: M=64 pixels (8h x 8w) x N=128 cout.  K=1152 in 8 chunks of 144
//   (16 channels x 9 taps).  Thread tile 4M x 8N; warp footprint 4x8.
//   Sampling meta lives in REGISTERS (fixed 9 units/thread across chunks).
//   smem = sB 73728 + sA 39168 = 112896 -> 2 blocks/SM.
// ============================================================================
#define SA_PITCH 68
#define SMEM_SB  0
#define SMEM_SA  73728
#define SMEM_TOT 112896

__global__ void __launch_bounds__(256, 2) k_gemm(const float* __restrict__ b_ker,
                                                 float* __restrict__ out) {
    extern __shared__ char smem[];
    float* sB = (float*)(smem + SMEM_SB);
    float* sA = (float*)(smem + SMEM_SA);
    const U32 sB_u32 = (U32)__cvta_generic_to_shared(sB);

    const int tid = threadIdx.x;
    const int b  = blockIdx.z;
    const int h0 = blockIdx.y * 8, w0 = blockIdx.x * 8;
    const int warp = tid >> 5, lane = tid & 31;
    const int ty = (warp & 3) * 4 + (lane >> 3);   // 0..15: pixels ty*4..+3
    const int tx = (warp >> 2) * 8 + (lane & 7);   // 0..15: couts tx*8..+7
    const int q  = tid >> 2;                        // gather corner-set base
    const int g4 = (tid & 3) << 2;                  // channel sub-offset 0/4/8/12

    // ---- sampling meta -> registers (9 fixed units per thread)
    int   mcode[9], mbase[9];
    float mfx[9], mfy[9];
    {
        const float2* uvp = (const float2*)g_UV;
#pragma unroll
        for (int it = 0; it < 9; ++it) {
            int s  = q + (it << 6);            // 0..575
            int pm = s / 9, n = s - pm * 9;
            int h = h0 + (pm >> 3), w = w0 + (pm & 7);
            float2 uv = uvp[(b * 4096 + h * 64 + w) * 9 + n];
            float xf = floorf(uv.x), yf = floorf(uv.y);
            int ix = (int)xf, iy = (int)yf;
            int code = ix * 64 + iy;
            if (ix < 63) code |= (1 << 12);
            if (iy < 63) code |= (1 << 13);
            mcode[it] = code;
            mfx[it] = uv.x - xf;
            mfy[it] = uv.y - yf;
            mbase[it] = (g4 * 9 + n) * SA_PITCH + pm;
        }
    }

    ULL acc[4][4];
#pragma unroll
    for (int m = 0; m < 4; ++m)
#pragma unroll
        for (int j = 0; j < 4; ++j) acc[m][j] = pack2(0.f, 0.f);

    const float* xTb = g_xT + ((long)b << 19);

    for (int cc = 0; cc < 8; ++cc) {
        // ---- B tile: 144x128 = 4608 float4 via cp.async (overlaps gather)
        {
            const float* wsrc = g_Wt + cc * 144 * 128;
#pragma unroll
            for (int it = 0; it < 18; ++it) {
                int e = tid + (it << 8);
                cp_async16(sB_u32 + e * 16, wsrc + e * 4);
            }
            asm volatile("cp.async.commit_group;\n" ::: "memory");
        }

        // ---- A tile gather: 4 threads cover one 64B (16-ch) corner slice.
        const int choff = cc * 16 + g4;
#pragma unroll
        for (int it = 0; it < 9; ++it) {
            int code = mcode[it];
            float fx = mfx[it], fy = mfy[it];
            const float* pb = xTb + ((long)(code & 4095) << 7) + choff;
            int dxs = (code & (1 << 12)) ? 8192 : 0;   // +1 row = 64*128 floats
            int dys = (code & (1 << 13)) ? 128  : 0;   // +1 col
            float4 v00 = *(const float4*)(pb);
            float4 v01 = *(const float4*)(pb + dys);
            float4 v10 = *(const float4*)(pb + dxs);
            float4 v11 = *(const float4*)(pb + dxs + dys);
            int ab = mbase[it];
            float r0, r1;
            r0 = v00.x + fy * (v01.x - v00.x);
            r1 = v10.x + fy * (v11.x - v10.x);
            sA[ab                   ] = r0 + fx * (r1 - r0);
            r0 = v00.y + fy * (v01.y - v00.y);
            r1 = v10.y + fy * (v11.y - v10.y);
            sA[ab + 1 * 9 * SA_PITCH] = r0 + fx * (r1 - r0);
            r0 = v00.z + fy * (v01.z - v00.z);
            r1 = v10.z + fy * (v11.z - v10.z);
            sA[ab + 2 * 9 * SA_PITCH] = r0 + fx * (r1 - r0);
            r0 = v00.w + fy * (v01.w - v00.w);
            r1 = v10.w + fy * (v11.w - v10.w);
            sA[ab + 3 * 9 * SA_PITCH] = r0 + fx * (r1 - r0);
        }
        asm volatile("cp.async.wait_group 0;\n" ::: "memory");
        __syncthreads();

        // ---- GEMM on the 144-deep chunk: 4M x 8N rank-1 updates
#pragma unroll 8
        for (int kk = 0; kk < 144; ++kk) {
            float4 a4 = *(const float4*)&sA[kk * SA_PITCH + (ty << 2)];
            ulonglong2 bl0 = *(const ulonglong2*)&sB[kk * 128 + (tx << 3)];
            ulonglong2 bl1 = *(const ulonglong2*)&sB[kk * 128 + (tx << 3) + 4];
            ULL a0 = pack2(a4.x, a4.x), a1 = pack2(a4.y, a4.y);
            ULL a2 = pack2(a4.z, a4.z), a3 = pack2(a4.w, a4.w);
            fma2(acc[0][0], a0, bl0.x); fma2(acc[0][1], a0, bl0.y);
            fma2(acc[0][2], a0, bl1.x); fma2(acc[0][3], a0, bl1.y);
            fma2(acc[1][0], a1, bl0.x); fma2(acc[1][1], a1, bl0.y);
            fma2(acc[1][2], a1, bl1.x); fma2(acc[1][3], a1, bl1.y);
            fma2(acc[2][0], a2, bl0.x); fma2(acc[2][1], a2, bl0.y);
            fma2(acc[2][2], a2, bl1.x); fma2(acc[2][3], a2, bl1.y);
            fma2(acc[3][0], a3, bl0.x); fma2(acc[3][1], a3, bl0.y);
            fma2(acc[3][2], a3, bl1.x); fma2(acc[3][3], a3, bl1.y);
        }
        __syncthreads();
    }

    // ---- epilogue: + bias.  Pixels ty*4..+3 = row h0+(ty>>1), 4 consecutive w.
    const int co0 = tx << 3;
    const int h = h0 + (ty >> 1);
    const int wb = w0 + ((ty & 1) << 2);
    float* op = out + (((long)(b * 128 + co0)) << 12) + (h << 6) + wb;
#pragma unroll
    for (int j = 0; j < 4; ++j) {
        float lo0, hi0, lo1, hi1, lo2, hi2, lo3, hi3;
        unpack2(acc[0][j], lo0, hi0);
        unpack2(acc[1][j], lo1, hi1);
        unpack2(acc[2][j], lo2, hi2);
        unpack2(acc[3][j], lo3, hi3);
        float bkl = b_ker[co0 + 2 * j];
        float bkh = b_ker[co0 + 2 * j + 1];
        float4 vl = make_float4(lo0 + bkl, lo1 + bkl, lo2 + bkl, lo3 + bkl);
        float4 vh = make_float4(hi0 + bkh, hi1 + bkh, hi2 + bkh, hi3 + bkh);
        *(float4*)(op + ((long)(2 * j) << 12))     = vl;
        *(float4*)(op + ((long)(2 * j + 1) << 12)) = vh;
    }
}

// ============================================================================
// launch
// ============================================================================
extern "C" void kernel_launch(void* const* d_in, const int* in_sizes, int n_in,
                              void* d_out, int out_size) {
    const float* x     = (const float*)d_in[0];
    const float* w_off = (const float*)d_in[1];
    const float* b_off = (const float*)d_in[2];
    const float* w_ker = (const float*)d_in[3];
    const float* b_ker = (const float*)d_in[4];
    float* out = (float*)d_out;

    cudaFuncSetAttribute(k_gemm, cudaFuncAttributeMaxDynamicSharedMemorySize,
                         SMEM_TOT);

    k_prep<<<4800, 256, 0, 0>>>(x, w_off, b_off, w_ker);
    k_gemm<<<dim3(8, 8, 8), 256, SMEM_TOT, 0>>>(b_ker, out);
}

// round 12
// speedup vs baseline: 1.4867x; 1.4867x over previous
#include <cuda_runtime.h>

typedef unsigned long long ULL;
typedef unsigned int U32;

// ---------------- device scratch (no allocations allowed) ----------------
__device__ float g_UV[8 * 64 * 64 * 9 * 2];      // (u,v) per (b,h,w,n)
__device__ float g_Wt[1152 * 128];               // Wt[k][cout]
__device__ float g_xT[8 * 4096 * 128];           // NHWC transpose of x (16.8 MB)

// ---------------- packed f32x2 helpers ----------------
__device__ __forceinline__ ULL pack2(float lo, float hi) {
    ULL r; asm("mov.b64 %0, {%1,%2};" : "=l"(r) : "f"(lo), "f"(hi)); return r;
}
__device__ __forceinline__ void unpack2(ULL v, float& lo, float& hi) {
    asm("mov.b64 {%0,%1}, %2;" : "=f"(lo), "=f"(hi) : "l"(v));
}
__device__ __forceinline__ void fma2(ULL& d, ULL a, ULL b) {
    asm("fma.rn.f32x2 %0, %1, %2, %0;" : "+l"(d) : "l"(a), "l"(b));
}
__device__ __forceinline__ void cp_async16(U32 saddr, const void* gptr) {
    asm volatile("cp.async.ca.shared.global [%0], [%1], 16;\n"
                 :: "r"(saddr), "l"(gptr) : "memory");
}

// ============================================================================
// Kernel 0: NCHW -> NHWC transpose.  x (8,128,4096) -> g_xT (8,4096,128)
// ============================================================================
__global__ void __launch_bounds__(256) k_tr(const float* __restrict__ x) {
    __shared__ float t[32][33];
    const int b  = blockIdx.z;
    const int s0 = blockIdx.x * 32;
    const int c0 = blockIdx.y * 32;
    const int tx = threadIdx.x, ty = threadIdx.y;   // (32, 8)
#pragma unroll
    for (int i = 0; i < 4; ++i) {
        int c = c0 + ty + i * 8;
        t[ty + i * 8][tx] = x[((b * 128 + c) << 12) + s0 + tx];
    }
    __syncthreads();
#pragma unroll
    for (int i = 0; i < 4; ++i) {
        int s = s0 + ty + i * 8;
        g_xT[(((b << 12) + s) << 7) + c0 + tx] = t[tx][ty + i * 8];
    }
}

// ============================================================================
// Kernel 1: offset conv (128->18, 3x3, pad 1) fused with sampling coords.
// ============================================================================
__global__ void __launch_bounds__(256) k_offset(const float* __restrict__ x,
                                                const float* __restrict__ w_off,
                                                const float* __restrict__ b_off) {
    __shared__ __align__(16) float sx[8][324];
    __shared__ __align__(16) float sw[8][9][20];

    const int tid = threadIdx.x;
    const int b  = blockIdx.z;
    const int h0 = blockIdx.y * 16, w0 = blockIdx.x * 16;
    const int px = tid & 15, py = tid >> 4;

    ULL acc[10];
#pragma unroll
    for (int i = 0; i < 9; ++i) acc[i] = pack2(b_off[2 * i], b_off[2 * i + 1]);
    acc[9] = pack2(0.f, 0.f);

    for (int cc = 0; cc < 16; ++cc) {
        for (int e = tid; e < 8 * 324; e += 256) {
            int c = e / 324; int rem = e - c * 324;
            int r = rem / 18, col = rem - r * 18;
            int gh = h0 + r - 1, gw = w0 + col - 1;
            float v = 0.f;
            if (gh >= 0 && gh < 64 && gw >= 0 && gw < 64)
                v = x[((b * 128 + cc * 8 + c) << 12) + (gh << 6) + gw];
            sx[c][rem] = v;
        }
        for (int e = tid; e < 8 * 180; e += 256) {
            int c = e / 180; int rem = e - c * 180;
            int tap = rem / 20, o = rem - tap * 20;
            sw[c][tap][o] = (o < 18) ? w_off[(o * 128 + cc * 8 + c) * 9 + tap] : 0.f;
        }
        __syncthreads();

#pragma unroll
        for (int c = 0; c < 8; ++c) {
#pragma unroll
            for (int i = 0; i < 3; ++i) {
#pragma unroll
                for (int j = 0; j < 3; ++j) {
                    float xv = sx[c][(py + i) * 18 + (px + j)];
                    ULL xp = pack2(xv, xv);
                    const ulonglong2* wp = (const ulonglong2*)sw[c][i * 3 + j];
                    ulonglong2 wA = wp[0], wB = wp[1], wC = wp[2], wD = wp[3], wE = wp[4];
                    fma2(acc[0], xp, wA.x); fma2(acc[1], xp, wA.y);
                    fma2(acc[2], xp, wB.x); fma2(acc[3], xp, wB.y);
                    fma2(acc[4], xp, wC.x); fma2(acc[5], xp, wC.y);
                    fma2(acc[6], xp, wD.x); fma2(acc[7], xp, wD.y);
                    fma2(acc[8], xp, wE.x); fma2(acc[9], xp, wE.y);
                }
            }
        }
        __syncthreads();
    }

    float offs[18];
#pragma unroll
    for (int i = 0; i < 9; ++i) unpack2(acc[i], offs[2 * i], offs[2 * i + 1]);

    const int h = h0 + py, w = w0 + px;
    float2* uvp = (float2*)g_UV;
    const int basei = (b * 4096 + h * 64 + w) * 9;
#pragma unroll
    for (int n = 0; n < 9; ++n) {
        float u = (float)(h + n / 3 - 1) + offs[n];
        float v = (float)(w + n % 3 - 1) + offs[9 + n];
        u = fminf(fmaxf(u, 0.f), 63.f);
        v = fminf(fmaxf(v, 0.f), 63.f);
        uvp[basei + n] = make_float2(u, v);
    }
}

// ============================================================================
// Kernel 2: weight transpose  Wt[k = c*9+tap][cout] = w_ker[cout][c][tap]
// ============================================================================
__global__ void k_wt(const float* __restrict__ w_ker) {
    int i = blockIdx.x * 256 + threadIdx.x;
    if (i < 1152 * 128) {
        int o = i / 1152, k = i - o * 1152;
        g_Wt[k * 128 + o] = w_ker[i];
    }
}

// ============================================================================
// Kernel 3: halo-smem bilinear gather + GEMM, 8Mx8N, 2 blocks/SM.
//   Block: M=128 pixels (16h x 8w) x N=128 cout.  K=1152 in 16 chunks of 72
//   (8 channels x 9 taps).  Per chunk: load 24x16 halo (8ch) coalesced into
//   smem, bilinear-interpolate FROM smem (global fallback if coord outside
//   halo).  110.2 KB smem -> 2 blocks/SM, 256 blocks = 1 wave.
// ============================================================================
#define SA_PITCH 132
#define SMEM_SB   0                                   // 72*128*4  = 36864
#define SMEM_SA   36864                               // 72*132*4  = 38016
#define SMEM_H    74880                               // 384*8*4   = 12288
#define SMEM_IDX  87168                               // 1152*4
#define SMEM_HP   91776                               // 1152*4
#define SMEM_FX   96384                               // 1152*4
#define SMEM_FY   100992                              // 1152*4
#define SMEM_STS  105600                              // 1152*4
#define SMEM_TOT  110208

__global__ void __launch_bounds__(256, 2) k_gemm(const float* __restrict__ b_ker,
                                                 float* __restrict__ out) {
    extern __shared__ char smem[];
    float* sB   = (float*)(smem + SMEM_SB);
    float* sA   = (float*)(smem + SMEM_SA);
    float* sH   = (float*)(smem + SMEM_H);
    int*   sIdx = (int*)  (smem + SMEM_IDX);
    int*   sHP  = (int*)  (smem + SMEM_HP);
    float* sFx  = (float*)(smem + SMEM_FX);
    float* sFy  = (float*)(smem + SMEM_FY);
    int*   sSts = (int*)  (smem + SMEM_STS);
    const U32 sB_u32 = (U32)__cvta_generic_to_shared(sB);

    const int tid = threadIdx.x;
    const int b  = blockIdx.z;
    const int h0 = blockIdx.y * 16, w0 = blockIdx.x * 8;
    const int tx = tid & 15;     // N: couts tx*8 .. tx*8+7
    const int ty = tid >> 4;     // M: row h0+ty, cols w0..w0+7

    // ---- stage sampling meta once per block: 1152 (pixel, tap) entries
    const float2* uvp = (const float2*)g_UV;
    for (int e = tid; e < 1152; e += 256) {
        int pm = e / 9, n = e - pm * 9;
        int h = h0 + (pm >> 3), w = w0 + (pm & 7);
        float2 uv = uvp[(b * 4096 + h * 64 + w) * 9 + n];
        float xf = floorf(uv.x), yf = floorf(uv.y);
        int ix = (int)xf, iy = (int)yf;
        int gcode = ix * 64 + iy;
        if (ix < 63) gcode |= (1 << 12);
        if (iy < 63) gcode |= (1 << 13);
        sIdx[e] = gcode;
        int hr = ix - (h0 - 4), wr = iy - (w0 - 4);
        int hcode = (hr * 16 + wr) & 4095;
        if (ix < 63) hcode |= (1 << 12);
        if (iy < 63) hcode |= (1 << 13);
        if (hr >= 0 && hr < 23 && wr >= 0 && wr < 15) hcode |= (1 << 14);
        sHP[e] = hcode;
        sFx[e] = uv.x - xf;
        sFy[e] = uv.y - yf;
        sSts[e] = n * SA_PITCH + pm;
    }

    ULL acc[8][4];
#pragma unroll
    for (int m = 0; m < 8; ++m)
#pragma unroll
        for (int j = 0; j < 4; ++j) acc[m][j] = pack2(0.f, 0.f);

    const float* xTb = g_xT + ((long)b << 19);
    __syncthreads();

    for (int cc = 0; cc < 16; ++cc) {
        const int chbase = cc * 8;

        // ---- B tile: 72x128 = 2304 float4 via cp.async (overlaps halo fill)
        {
            const float* wsrc = g_Wt + cc * 72 * 128;
#pragma unroll
            for (int it = 0; it < 9; ++it) {
                int e = tid + (it << 8);
                cp_async16(sB_u32 + e * 16, wsrc + e * 4);
            }
            asm volatile("cp.async.commit_group;\n" ::: "memory");
        }

        // ---- halo fill: 24x16 positions x 8 ch, coalesced from NHWC
#pragma unroll
        for (int it = 0; it < 3; ++it) {
            int e = tid + (it << 8);          // 0..767
            int pos = e >> 1, g = e & 1;
            int hr = pos >> 4, wr = pos & 15;
            int gh = min(max(h0 - 4 + hr, 0), 63);
            int gw = min(max(w0 - 4 + wr, 0), 63);
            *(float4*)&sH[(pos << 3) + (g << 2)] =
                *(const float4*)(xTb + ((long)((gh << 6) + gw) << 7) + chbase + (g << 2));
        }
        __syncthreads();

        // ---- bilinear from halo smem (global fallback, ~never taken)
#pragma unroll
        for (int it = 0; it < 9; ++it) {
            int u = tid + (it << 8);
            int p = u >> 1, g = u & 1;
            float fx = sFx[p], fy = sFy[p];
            int hc = sHP[p];
            int abase = sSts[p] + (g << 2) * (9 * SA_PITCH);
            float4 v00, v01, v10, v11;
            if (hc & (1 << 14)) {
                const float* cb = sH + ((hc & 4095) << 3) + (g << 2);
                int dxs = (hc & (1 << 12)) ? 128 : 0;   // +1 halo row = 16*8
                int dys = (hc & (1 << 13)) ? 8   : 0;   // +1 halo col
                v00 = *(const float4*)(cb);
                v01 = *(const float4*)(cb + dys);
                v10 = *(const float4*)(cb + dxs);
                v11 = *(const float4*)(cb + dxs + dys);
            } else {
                int gc = sIdx[p];
                const float* pb = xTb + ((long)(gc & 4095) << 7) + chbase + (g << 2);
                int dxs = (gc & (1 << 12)) ? 8192 : 0;
                int dys = (gc & (1 << 13)) ? 128  : 0;
                v00 = *(const float4*)(pb);
                v01 = *(const float4*)(pb + dys);
                v10 = *(const float4*)(pb + dxs);
                v11 = *(const float4*)(pb + dxs + dys);
            }
            float r0, r1;
            r0 = v00.x + fy * (v01.x - v00.x);
            r1 = v10.x + fy * (v11.x - v10.x);
            sA[abase                   ] = r0 + fx * (r1 - r0);
            r0 = v00.y + fy * (v01.y - v00.y);
            r1 = v10.y + fy * (v11.y - v10.y);
            sA[abase + 1 * 9 * SA_PITCH] = r0 + fx * (r1 - r0);
            r0 = v00.z + fy * (v01.z - v00.z);
            r1 = v10.z + fy * (v11.z - v10.z);
            sA[abase + 2 * 9 * SA_PITCH] = r0 + fx * (r1 - r0);
            r0 = v00.w + fy * (v01.w - v00.w);
            r1 = v10.w + fy * (v11.w - v10.w);
            sA[abase + 3 * 9 * SA_PITCH] = r0 + fx * (r1 - r0);
        }
        asm volatile("cp.async.wait_group 0;\n" ::: "memory");
        __syncthreads();

        // ---- GEMM on the 72-deep chunk: 8M x 8N rank-1 updates
#pragma unroll 8
        for (int kk = 0; kk < 72; ++kk) {
            float4 aL = *(const float4*)&sA[kk * SA_PITCH + (ty << 3)];
            float4 aH = *(const float4*)&sA[kk * SA_PITCH + (ty << 3) + 4];
            ulonglong2 bl0 = *(const ulonglong2*)&sB[kk * 128 + (tx << 3)];
            ulonglong2 bl1 = *(const ulonglong2*)&sB[kk * 128 + (tx << 3) + 4];
            ULL a0 = pack2(aL.x, aL.x), a1 = pack2(aL.y, aL.y);
            ULL a2 = pack2(aL.z, aL.z), a3 = pack2(aL.w, aL.w);
            ULL a4 = pack2(aH.x, aH.x), a5 = pack2(aH.y, aH.y);
            ULL a6 = pack2(aH.z, aH.z), a7 = pack2(aH.w, aH.w);
            fma2(acc[0][0], a0, bl0.x); fma2(acc[0][1], a0, bl0.y);
            fma2(acc[0][2], a0, bl1.x); fma2(acc[0][3], a0, bl1.y);
            fma2(acc[1][0], a1, bl0.x); fma2(acc[1][1], a1, bl0.y);
            fma2(acc[1][2], a1, bl1.x); fma2(acc[1][3], a1, bl1.y);
            fma2(acc[2][0], a2, bl0.x); fma2(acc[2][1], a2, bl0.y);
            fma2(acc[2][2], a2, bl1.x); fma2(acc[2][3], a2, bl1.y);
            fma2(acc[3][0], a3, bl0.x); fma2(acc[3][1], a3, bl0.y);
            fma2(acc[3][2], a3, bl1.x); fma2(acc[3][3], a3, bl1.y);
            fma2(acc[4][0], a4, bl0.x); fma2(acc[4][1], a4, bl0.y);
            fma2(acc[4][2], a4, bl1.x); fma2(acc[4][3], a4, bl1.y);
            fma2(acc[5][0], a5, bl0.x); fma2(acc[5][1], a5, bl0.y);
            fma2(acc[5][2], a5, bl1.x); fma2(acc[5][3], a5, bl1.y);
            fma2(acc[6][0], a6, bl0.x); fma2(acc[6][1], a6, bl0.y);
            fma2(acc[6][2], a6, bl1.x); fma2(acc[6][3], a6, bl1.y);
            fma2(acc[7][0], a7, bl0.x); fma2(acc[7][1], a7, bl0.y);
            fma2(acc[7][2], a7, bl1.x); fma2(acc[7][3], a7, bl1.y);
        }
        __syncthreads();
    }

    // ---- epilogue: + bias.  Thread owns row h0+ty, w0..w0+7, couts tx*8+0..7.
    const int co0 = tx << 3;
    const int h = h0 + ty;
    float* op = out + (((long)(b * 128 + co0)) << 12) + (h << 6) + w0;
#pragma unroll
    for (int j = 0; j < 4; ++j) {
        float lo[8], hi[8];
#pragma unroll
        for (int m = 0; m < 8; ++m) unpack2(acc[m][j], lo[m], hi[m]);
        float bkl = b_ker[co0 + 2 * j];
        float bkh = b_ker[co0 + 2 * j + 1];
        float* o0 = op + ((long)(2 * j) << 12);
        float* o1 = op + ((long)(2 * j + 1) << 12);
        *(float4*)(o0)     = make_float4(lo[0] + bkl, lo[1] + bkl, lo[2] + bkl, lo[3] + bkl);
        *(float4*)(o0 + 4) = make_float4(lo[4] + bkl, lo[5] + bkl, lo[6] + bkl, lo[7] + bkl);
        *(float4*)(o1)     = make_float4(hi[0] + bkh, hi[1] + bkh, hi[2] + bkh, hi[3] + bkh);
        *(float4*)(o1 + 4) = make_float4(hi[4] + bkh, hi[5] + bkh, hi[6] + bkh, hi[7] + bkh);
    }
}

// ============================================================================
// launch
// ============================================================================
extern "C" void kernel_launch(void* const* d_in, const int* in_sizes, int n_in,
                              void* d_out, int out_size) {
    const float* x     = (const float*)d_in[0];
    const float* w_off = (const float*)d_in[1];
    const float* b_off = (const float*)d_in[2];
    const float* w_ker = (const float*)d_in[3];
    const float* b_ker = (const float*)d_in[4];
    float* out = (float*)d_out;

    cudaFuncSetAttribute(k_gemm, cudaFuncAttributeMaxDynamicSharedMemorySize,
                         SMEM_TOT);

    k_wt<<<(1152 * 128 + 255) / 256, 256, 0, 0>>>(w_ker);
    k_tr<<<dim3(128, 4, 8), dim3(32, 8), 0, 0>>>(x);
    k_offset<<<dim3(4, 4, 8), 256, 0, 0>>>(x, w_off, b_off);
    k_gemm<<<dim3(8, 4, 8), 256, SMEM_TOT, 0>>>(b_ker, out);
}

// round 13
// speedup vs baseline: 1.5109x; 1.0163x over previous
#include <cuda_runtime.h>

typedef unsigned long long ULL;
typedef unsigned int U32;

// ---------------- device scratch (no allocations allowed) ----------------
__device__ float g_UV[8 * 64 * 64 * 9 * 2];      // (u,v) per (b,h,w,n)
__device__ float g_Wt[1152 * 128];               // Wt[k][cout]
__device__ float g_xT[8 * 4096 * 128];           // NHWC transpose of x (16.8 MB)

// ---------------- packed f32x2 helpers ----------------
__device__ __forceinline__ ULL pack2(float lo, float hi) {
    ULL r; asm("mov.b64 %0, {%1,%2};" : "=l"(r) : "f"(lo), "f"(hi)); return r;
}
__device__ __forceinline__ void unpack2(ULL v, float& lo, float& hi) {
    asm("mov.b64 {%0,%1}, %2;" : "=f"(lo), "=f"(hi) : "l"(v));
}
__device__ __forceinline__ void fma2(ULL& d, ULL a, ULL b) {
    asm("fma.rn.f32x2 %0, %1, %2, %0;" : "+l"(d) : "l"(a), "l"(b));
}
__device__ __forceinline__ void cp_async16(U32 saddr, const void* gptr) {
    asm volatile("cp.async.ca.shared.global [%0], [%1], 16;\n"
                 :: "r"(saddr), "l"(gptr) : "memory");
}

// ============================================================================
// Kernel 0: NCHW -> NHWC transpose.  x (8,128,4096) -> g_xT (8,4096,128)
// ============================================================================
__global__ void __launch_bounds__(256) k_tr(const float* __restrict__ x) {
    __shared__ float t[32][33];
    const int b  = blockIdx.z;
    const int s0 = blockIdx.x * 32;
    const int c0 = blockIdx.y * 32;
    const int tx = threadIdx.x, ty = threadIdx.y;   // (32, 8)
#pragma unroll
    for (int i = 0; i < 4; ++i) {
        int c = c0 + ty + i * 8;
        t[ty + i * 8][tx] = x[((b * 128 + c) << 12) + s0 + tx];
    }
    __syncthreads();
#pragma unroll
    for (int i = 0; i < 4; ++i) {
        int s = s0 + ty + i * 8;
        g_xT[(((b << 12) + s) << 7) + c0 + tx] = t[tx][ty + i * 8];
    }
}

// ============================================================================
// Kernel 1: offset conv (128->18, 3x3, pad 1) fused with sampling coords.
// ============================================================================
__global__ void __launch_bounds__(256) k_offset(const float* __restrict__ x,
                                                const float* __restrict__ w_off,
                                                const float* __restrict__ b_off) {
    __shared__ __align__(16) float sx[8][324];
    __shared__ __align__(16) float sw[8][9][20];

    const int tid = threadIdx.x;
    const int b  = blockIdx.z;
    const int h0 = blockIdx.y * 16, w0 = blockIdx.x * 16;
    const int px = tid & 15, py = tid >> 4;

    ULL acc[10];
#pragma unroll
    for (int i = 0; i < 9; ++i) acc[i] = pack2(b_off[2 * i], b_off[2 * i + 1]);
    acc[9] = pack2(0.f, 0.f);

    for (int cc = 0; cc < 16; ++cc) {
        for (int e = tid; e < 8 * 324; e += 256) {
            int c = e / 324; int rem = e - c * 324;
            int r = rem / 18, col = rem - r * 18;
            int gh = h0 + r - 1, gw = w0 + col - 1;
            float v = 0.f;
            if (gh >= 0 && gh < 64 && gw >= 0 && gw < 64)
                v = x[((b * 128 + cc * 8 + c) << 12) + (gh << 6) + gw];
            sx[c][rem] = v;
        }
        for (int e = tid; e < 8 * 180; e += 256) {
            int c = e / 180; int rem = e - c * 180;
            int tap = rem / 20, o = rem - tap * 20;
            sw[c][tap][o] = (o < 18) ? w_off[(o * 128 + cc * 8 + c) * 9 + tap] : 0.f;
        }
        __syncthreads();

#pragma unroll
        for (int c = 0; c < 8; ++c) {
#pragma unroll
            for (int i = 0; i < 3; ++i) {
#pragma unroll
                for (int j = 0; j < 3; ++j) {
                    float xv = sx[c][(py + i) * 18 + (px + j)];
                    ULL xp = pack2(xv, xv);
                    const ulonglong2* wp = (const ulonglong2*)sw[c][i * 3 + j];
                    ulonglong2 wA = wp[0], wB = wp[1], wC = wp[2], wD = wp[3], wE = wp[4];
                    fma2(acc[0], xp, wA.x); fma2(acc[1], xp, wA.y);
                    fma2(acc[2], xp, wB.x); fma2(acc[3], xp, wB.y);
                    fma2(acc[4], xp, wC.x); fma2(acc[5], xp, wC.y);
                    fma2(acc[6], xp, wD.x); fma2(acc[7], xp, wD.y);
                    fma2(acc[8], xp, wE.x); fma2(acc[9], xp, wE.y);
                }
            }
        }
        __syncthreads();
    }

    float offs[18];
#pragma unroll
    for (int i = 0; i < 9; ++i) unpack2(acc[i], offs[2 * i], offs[2 * i + 1]);

    const int h = h0 + py, w = w0 + px;
    float2* uvp = (float2*)g_UV;
    const int basei = (b * 4096 + h * 64 + w) * 9;
#pragma unroll
    for (int n = 0; n < 9; ++n) {
        float u = (float)(h + n / 3 - 1) + offs[n];
        float v = (float)(w + n % 3 - 1) + offs[9 + n];
        u = fminf(fmaxf(u, 0.f), 63.f);
        v = fminf(fmaxf(v, 0.f), 63.f);
        uvp[basei + n] = make_float2(u, v);
    }
}

// ============================================================================
// Kernel 2: weight transpose  Wt[k = c*9+tap][cout] = w_ker[cout][c][tap]
// ============================================================================
__global__ void k_wt(const float* __restrict__ w_ker) {
    int i = blockIdx.x * 256 + threadIdx.x;
    if (i < 1152 * 128) {
        int o = i / 1152, k = i - o * 1152;
        g_Wt[k * 128 + o] = w_ker[i];
    }
}

// ============================================================================
// Kernel 3: halo-smem bilinear gather + GEMM, bank-tuned layouts.
//   Block: M=128 pixels (16h x 8w) x N=128 cout.  K=1152 in 16 chunks of 72.
//   sA layout: [pxgroup 0..15][kk 0..71][8 px], group pitch 580 floats
//   (2320 B = 4 banks mod 32) -> conflict-free A loads AND coalesced STS.
//   Warp footprint 8ty x 4tx -> 4 LDS wavefronts per warp per kk.
//   104.7 KB smem -> 2 blocks/SM, 256 blocks = 1 wave.
// ============================================================================
#define SA_GP    580                                 // floats per pixel-group
#define SMEM_SB   0                                  // 72*128*4  = 36864
#define SMEM_SA   36864                              // 16*580*4  = 37120
#define SMEM_H    73984                              // 384*8*4   = 12288
#define SMEM_IDX  86272                              // 1152*4
#define SMEM_HP   90880                              // 1152*4
#define SMEM_FX   95488                              // 1152*4
#define SMEM_FY   100096                             // 1152*4
#define SMEM_TOT  104704

__global__ void __launch_bounds__(256, 2) k_gemm(const float* __restrict__ b_ker,
                                                 float* __restrict__ out) {
    extern __shared__ char smem[];
    float* sB   = (float*)(smem + SMEM_SB);
    float* sA   = (float*)(smem + SMEM_SA);
    float* sH   = (float*)(smem + SMEM_H);
    int*   sIdx = (int*)  (smem + SMEM_IDX);
    int*   sHP  = (int*)  (smem + SMEM_HP);
    float* sFx  = (float*)(smem + SMEM_FX);
    float* sFy  = (float*)(smem + SMEM_FY);
    const U32 sB_u32 = (U32)__cvta_generic_to_shared(sB);

    const int tid = threadIdx.x;
    const int b  = blockIdx.z;
    const int h0 = blockIdx.y * 16, w0 = blockIdx.x * 8;
    const int warp = tid >> 5, lane = tid & 31;
    const int ty = ((warp & 1) << 3) | (lane >> 2);   // 0..15 pixel-group
    const int tx = ((warp >> 1) << 2) | (lane & 3);   // 0..15 cout-group

    // gather identity: pm = tid&127 (pixel), chg = tid>>7 (channel half)
    const int pm  = tid & 127;
    const int chg = tid >> 7;

    // ---- stage sampling meta once per block, keyed [n][pm]
    const float2* uvp = (const float2*)g_UV;
    for (int e = tid; e < 1152; e += 256) {
        int n = e >> 7, pp = e & 127;
        int h = h0 + (pp >> 3), w = w0 + (pp & 7);
        float2 uv = uvp[(b * 4096 + h * 64 + w) * 9 + n];
        float xf = floorf(uv.x), yf = floorf(uv.y);
        int ix = (int)xf, iy = (int)yf;
        int gcode = ix * 64 + iy;
        if (ix < 63) gcode |= (1 << 12);
        if (iy < 63) gcode |= (1 << 13);
        sIdx[e] = gcode;
        int hr = ix - (h0 - 4), wr = iy - (w0 - 4);
        int hcode = (hr * 16 + wr) & 4095;
        if (ix < 63) hcode |= (1 << 12);
        if (iy < 63) hcode |= (1 << 13);
        if (hr >= 0 && hr < 23 && wr >= 0 && wr < 15) hcode |= (1 << 14);
        sHP[e] = hcode;
        sFx[e] = uv.x - xf;
        sFy[e] = uv.y - yf;
    }

    ULL acc[8][4];
#pragma unroll
    for (int m = 0; m < 8; ++m)
#pragma unroll
        for (int j = 0; j < 4; ++j) acc[m][j] = pack2(0.f, 0.f);

    const float* xTb = g_xT + ((long)b << 19);
    // sA store base for this thread: group (pm>>3), sub-pixel (pm&7)
    const int sa_base = (pm >> 3) * SA_GP + (pm & 7);
    __syncthreads();

    for (int cc = 0; cc < 16; ++cc) {
        const int chbase = cc * 8;

        // ---- B tile: 72x128 = 2304 float4 via cp.async (overlaps halo fill)
        {
            const float* wsrc = g_Wt + cc * 72 * 128;
#pragma unroll
            for (int it = 0; it < 9; ++it) {
                int e = tid + (it << 8);
                cp_async16(sB_u32 + e * 16, wsrc + e * 4);
            }
            asm volatile("cp.async.commit_group;\n" ::: "memory");
        }

        // ---- halo fill: 24x16 positions x 8 ch, coalesced from NHWC
#pragma unroll
        for (int it = 0; it < 3; ++it) {
            int e = tid + (it << 8);          // 0..767
            int pos = e >> 1, g = e & 1;
            int hr = pos >> 4, wr = pos & 15;
            int gh = min(max(h0 - 4 + hr, 0), 63);
            int gw = min(max(w0 - 4 + wr, 0), 63);
            *(float4*)&sH[(pos << 3) + (g << 2)] =
                *(const float4*)(xTb + ((long)((gh << 6) + gw) << 7) + chbase + (g << 2));
        }
        __syncthreads();

        // ---- bilinear from halo smem; warp = 32 consecutive pm at fixed (n,chg)
        //      -> coalesced STS into sA.
#pragma unroll
        for (int n = 0; n < 9; ++n) {
            int p = (n << 7) + pm;
            float fx = sFx[p], fy = sFy[p];
            int hc = sHP[p];
            float4 v00, v01, v10, v11;
            if (hc & (1 << 14)) {
                const float* cb = sH + ((hc & 4095) << 3) + (chg << 2);
                int dxs = (hc & (1 << 12)) ? 128 : 0;   // +1 halo row = 16*8
                int dys = (hc & (1 << 13)) ? 8   : 0;   // +1 halo col
                v00 = *(const float4*)(cb);
                v01 = *(const float4*)(cb + dys);
                v10 = *(const float4*)(cb + dxs);
                v11 = *(const float4*)(cb + dxs + dys);
            } else {
                int gc = sIdx[p];
                const float* pb = xTb + ((long)(gc & 4095) << 7) + chbase + (chg << 2);
                int dxs = (gc & (1 << 12)) ? 8192 : 0;
                int dys = (gc & (1 << 13)) ? 128  : 0;
                v00 = *(const float4*)(pb);
                v01 = *(const float4*)(pb + dys);
                v10 = *(const float4*)(pb + dxs);
                v11 = *(const float4*)(pb + dxs + dys);
            }
            // k rows: (chg*4 + ci)*9 + n
            int ab = sa_base + (((chg << 2) * 9 + n) << 3);
            float r0, r1;
            r0 = v00.x + fy * (v01.x - v00.x);
            r1 = v10.x + fy * (v11.x - v10.x);
            sA[ab          ] = r0 + fx * (r1 - r0);
            r0 = v00.y + fy * (v01.y - v00.y);
            r1 = v10.y + fy * (v11.y - v10.y);
            sA[ab + 9 * 8  ] = r0 + fx * (r1 - r0);
            r0 = v00.z + fy * (v01.z - v00.z);
            r1 = v10.z + fy * (v11.z - v10.z);
            sA[ab + 18 * 8 ] = r0 + fx * (r1 - r0);
            r0 = v00.w + fy * (v01.w - v00.w);
            r1 = v10.w + fy * (v11.w - v10.w);
            sA[ab + 27 * 8 ] = r0 + fx * (r1 - r0);
        }
        asm volatile("cp.async.wait_group 0;\n" ::: "memory");
        __syncthreads();

        // ---- GEMM on the 72-deep chunk: 8M x 8N rank-1 updates
        const float* aRow = sA + ty * SA_GP;
#pragma unroll 8
        for (int kk = 0; kk < 72; ++kk) {
            float4 aL = *(const float4*)(aRow + (kk << 3));
            float4 aH = *(const float4*)(aRow + (kk << 3) + 4);
            ulonglong2 bl0 = *(const ulonglong2*)&sB[kk * 128 + (tx << 3)];
            ulonglong2 bl1 = *(const ulonglong2*)&sB[kk * 128 + (tx << 3) + 4];
            ULL a0 = pack2(aL.x, aL.x), a1 = pack2(aL.y, aL.y);
            ULL a2 = pack2(aL.z, aL.z), a3 = pack2(aL.w, aL.w);
            ULL a4 = pack2(aH.x, aH.x), a5 = pack2(aH.y, aH.y);
            ULL a6 = pack2(aH.z, aH.z), a7 = pack2(aH.w, aH.w);
            fma2(acc[0][0], a0, bl0.x); fma2(acc[0][1], a0, bl0.y);
            fma2(acc[0][2], a0, bl1.x); fma2(acc[0][3], a0, bl1.y);
            fma2(acc[1][0], a1, bl0.x); fma2(acc[1][1], a1, bl0.y);
            fma2(acc[1][2], a1, bl1.x); fma2(acc[1][3], a1, bl1.y);
            fma2(acc[2][0], a2, bl0.x); fma2(acc[2][1], a2, bl0.y);
            fma2(acc[2][2], a2, bl1.x); fma2(acc[2][3], a2, bl1.y);
            fma2(acc[3][0], a3, bl0.x); fma2(acc[3][1], a3, bl0.y);
            fma2(acc[3][2], a3, bl1.x); fma2(acc[3][3], a3, bl1.y);
            fma2(acc[4][0], a4, bl0.x); fma2(acc[4][1], a4, bl0.y);
            fma2(acc[4][2], a4, bl1.x); fma2(acc[4][3], a4, bl1.y);
            fma2(acc[5][0], a5, bl0.x); fma2(acc[5][1], a5, bl0.y);
            fma2(acc[5][2], a5, bl1.x); fma2(acc[5][3], a5, bl1.y);
            fma2(acc[6][0], a6, bl0.x); fma2(acc[6][1], a6, bl0.y);
            fma2(acc[6][2], a6, bl1.x); fma2(acc[6][3], a6, bl1.y);
            fma2(acc[7][0], a7, bl0.x); fma2(acc[7][1], a7, bl0.y);
            fma2(acc[7][2], a7, bl1.x); fma2(acc[7][3], a7, bl1.y);
        }
        __syncthreads();
    }

    // ---- epilogue: + bias.  Thread owns row h0+ty, w0..w0+7, couts tx*8+0..7.
    const int co0 = tx << 3;
    const int h = h0 + ty;
    float* op = out + (((long)(b * 128 + co0)) << 12) + (h << 6) + w0;
#pragma unroll
    for (int j = 0; j < 4; ++j) {
        float lo[8], hi[8];
#pragma unroll
        for (int m = 0; m < 8; ++m) unpack2(acc[m][j], lo[m], hi[m]);
        float bkl = b_ker[co0 + 2 * j];
        float bkh = b_ker[co0 + 2 * j + 1];
        float* o0 = op + ((long)(2 * j) << 12);
        float* o1 = op + ((long)(2 * j + 1) << 12);
        *(float4*)(o0)     = make_float4(lo[0] + bkl, lo[1] + bkl, lo[2] + bkl, lo[3] + bkl);
        *(float4*)(o0 + 4) = make_float4(lo[4] + bkl, lo[5] + bkl, lo[6] + bkl, lo[7] + bkl);
        *(float4*)(o1)     = make_float4(hi[0] + bkh, hi[1] + bkh, hi[2] + bkh, hi[3] + bkh);
        *(float4*)(o1 + 4) = make_float4(hi[4] + bkh, hi[5] + bkh, hi[6] + bkh, hi[7] + bkh);
    }
}

// ============================================================================
// launch
// ============================================================================
extern "C" void kernel_launch(void* const* d_in, const int* in_sizes, int n_in,
                              void* d_out, int out_size) {
    const float* x     = (const float*)d_in[0];
    const float* w_off = (const float*)d_in[1];
    const float* b_off = (const float*)d_in[2];
    const float* w_ker = (const float*)d_in[3];
    const float* b_ker = (const float*)d_in[4];
    float* out = (float*)d_out;

    cudaFuncSetAttribute(k_gemm, cudaFuncAttributeMaxDynamicSharedMemorySize,
                         SMEM_TOT);

    k_wt<<<(1152 * 128 + 255) / 256, 256, 0, 0>>>(w_ker);
    k_tr<<<dim3(128, 4, 8), dim3(32, 8), 0, 0>>>(x);
    k_offset<<<dim3(4, 4, 8), 256, 0, 0>>>(x, w_off, b_off);
    k_gemm<<<dim3(8, 4, 8), 256, SMEM_TOT, 0>>>(b_ker, out);
}

// round 14
// speedup vs baseline: 1.5270x; 1.0106x over previous
#include <cuda_runtime.h>

typedef unsigned long long ULL;
typedef unsigned int U32;

// ---------------- device scratch (no allocations allowed) ----------------
__device__ float g_UV[8 * 64 * 64 * 9 * 2];      // (u,v) per (b,h,w,n)
__device__ float g_Wt[1152 * 128];               // Wt[k][cout]
__device__ float g_xT[8 * 4096 * 128];           // NHWC transpose of x (16.8 MB)

// ---------------- packed f32x2 helpers ----------------
__device__ __forceinline__ ULL pack2(float lo, float hi) {
    ULL r; asm("mov.b64 %0, {%1,%2};" : "=l"(r) : "f"(lo), "f"(hi)); return r;
}
__device__ __forceinline__ void unpack2(ULL v, float& lo, float& hi) {
    asm("mov.b64 {%0,%1}, %2;" : "=f"(lo), "=f"(hi) : "l"(v));
}
__device__ __forceinline__ void fma2(ULL& d, ULL a, ULL b) {
    asm("fma.rn.f32x2 %0, %1, %2, %0;" : "+l"(d) : "l"(a), "l"(b));
}
__device__ __forceinline__ void cp_async16(U32 saddr, const void* gptr) {
    asm volatile("cp.async.ca.shared.global [%0], [%1], 16;\n"
                 :: "r"(saddr), "l"(gptr) : "memory");
}

// ============================================================================
// Kernel 0: NCHW -> NHWC transpose.  x (8,128,4096) -> g_xT (8,4096,128)
// ============================================================================
__global__ void __launch_bounds__(256) k_tr(const float* __restrict__ x) {
    __shared__ float t[32][33];
    const int b  = blockIdx.z;
    const int s0 = blockIdx.x * 32;
    const int c0 = blockIdx.y * 32;
    const int tx = threadIdx.x, ty = threadIdx.y;   // (32, 8)
#pragma unroll
    for (int i = 0; i < 4; ++i) {
        int c = c0 + ty + i * 8;
        t[ty + i * 8][tx] = x[((b * 128 + c) << 12) + s0 + tx];
    }
    __syncthreads();
#pragma unroll
    for (int i = 0; i < 4; ++i) {
        int s = s0 + ty + i * 8;
        g_xT[(((b << 12) + s) << 7) + c0 + tx] = t[tx][ty + i * 8];
    }
}

// ============================================================================
// Kernel 1: offset conv (128->18, 3x3, pad 1), 512 threads: two halves each
// reduce 64 channels (even/odd 8-ch chunks), combined via smem at the end.
// ============================================================================
__global__ void __launch_bounds__(512) k_offset(const float* __restrict__ x,
                                                const float* __restrict__ w_off,
                                                const float* __restrict__ b_off) {
    // layout: sx[2][8][324] (5184 f) | sw[2][8][9][20] (2880 f) = 8064 floats.
    // After the loop the same buffer is reused for the 256x20 reduction.
    __shared__ __align__(16) float sbuf[8064];
    float* sxA = sbuf;            // [2][2592]
    float* swA = sbuf + 5184;     // [2][1440]

    const int tid  = threadIdx.x;
    const int half = tid >> 8;
    const int p    = tid & 255;
    const int b  = blockIdx.z;
    const int h0 = blockIdx.y * 16, w0 = blockIdx.x * 16;
    const int px = p & 15, py = p >> 4;

    ULL acc[10];
    if (half == 0) {
#pragma unroll
        for (int i = 0; i < 9; ++i) acc[i] = pack2(b_off[2 * i], b_off[2 * i + 1]);
        acc[9] = pack2(0.f, 0.f);
    } else {
#pragma unroll
        for (int i = 0; i < 10; ++i) acc[i] = pack2(0.f, 0.f);
    }

    float* msx = sxA + half * 2592;
    float* msw = swA + half * 1440;

    for (int i = 0; i < 8; ++i) {
        const int cc = (i << 1) | half;
        for (int e = p; e < 2592; e += 256) {
            int c = e / 324; int rem = e - c * 324;
            int r = rem / 18, col = rem - r * 18;
            int gh = h0 + r - 1, gw = w0 + col - 1;
            float v = 0.f;
            if (gh >= 0 && gh < 64 && gw >= 0 && gw < 64)
                v = x[((b * 128 + cc * 8 + c) << 12) + (gh << 6) + gw];
            msx[e] = v;
        }
        for (int e = p; e < 1440; e += 256) {
            int c = e / 180; int rem = e - c * 180;
            int tap = rem / 20, o = rem - tap * 20;
            msw[(c * 9 + tap) * 20 + o] =
                (o < 18) ? w_off[(o * 128 + cc * 8 + c) * 9 + tap] : 0.f;
        }
        __syncthreads();

#pragma unroll
        for (int c = 0; c < 8; ++c) {
#pragma unroll
            for (int ii = 0; ii < 3; ++ii) {
#pragma unroll
                for (int j = 0; j < 3; ++j) {
                    float xv = msx[c * 324 + (py + ii) * 18 + (px + j)];
                    ULL xp = pack2(xv, xv);
                    const ulonglong2* wp =
                        (const ulonglong2*)&msw[(c * 9 + ii * 3 + j) * 20];
                    ulonglong2 wA = wp[0], wB = wp[1], wC = wp[2], wD = wp[3], wE = wp[4];
                    fma2(acc[0], xp, wA.x); fma2(acc[1], xp, wA.y);
                    fma2(acc[2], xp, wB.x); fma2(acc[3], xp, wB.y);
                    fma2(acc[4], xp, wC.x); fma2(acc[5], xp, wC.y);
                    fma2(acc[6], xp, wD.x); fma2(acc[7], xp, wD.y);
                    fma2(acc[8], xp, wE.x); fma2(acc[9], xp, wE.y);
                }
            }
        }
        __syncthreads();
    }

    float offs[18];
#pragma unroll
    for (int i = 0; i < 9; ++i) unpack2(acc[i], offs[2 * i], offs[2 * i + 1]);

    if (half == 1) {
#pragma unroll
        for (int j = 0; j < 18; ++j) sbuf[p * 20 + j] = offs[j];
    }
    __syncthreads();
    if (half == 0) {
#pragma unroll
        for (int j = 0; j < 18; ++j) offs[j] += sbuf[p * 20 + j];

        const int h = h0 + py, w = w0 + px;
        float2* uvp = (float2*)g_UV;
        const int basei = (b * 4096 + h * 64 + w) * 9;
#pragma unroll
        for (int n = 0; n < 9; ++n) {
            float u = (float)(h + n / 3 - 1) + offs[n];
            float v = (float)(w + n % 3 - 1) + offs[9 + n];
            u = fminf(fmaxf(u, 0.f), 63.f);
            v = fminf(fmaxf(v, 0.f), 63.f);
            uvp[basei + n] = make_float2(u, v);
        }
    }
}

// ============================================================================
// Kernel 2: weight transpose  Wt[k = c*9+tap][cout] = w_ker[cout][c][tap]
// ============================================================================
__global__ void k_wt(const float* __restrict__ w_ker) {
    int i = blockIdx.x * 256 + threadIdx.x;
    if (i < 1152 * 128) {
        int o = i / 1152, k = i - o * 1152;
        g_Wt[k * 128 + o] = w_ker[i];
    }
}

// ============================================================================
// Kernel 3: halo-smem bilinear gather + GEMM, double-buffered halo prefetch.
//   Block: M=128 pixels (16h x 8w) x N=128 cout.  K=1152 in 16 chunks of 72.
//   Halo (24x16 pos, pitch 17, 8 ch) for chunk cc+1 is cp.async-prefetched
//   during GEMM(cc).  sA: [pxgroup][kk][8px], pitch 580 (bank-clean).
//   113.9 KB smem -> 2 blocks/SM, 256 blocks = 1 wave.
// ============================================================================
#define SA_GP    580
#define HPITCH   17
#define SMEM_SB   0                                  // 72*128*4   = 36864
#define SMEM_SA   36864                              // 16*580*4   = 37120
#define SMEM_H0   73984                              // 24*17*8*4  = 13056
#define SMEM_H1   87040                              // 13056
#define SMEM_CODE 100096                             // 1152*4
#define SMEM_FX   104704                             // 1152*4
#define SMEM_FY   109312                             // 1152*4
#define SMEM_TOT  113920

__global__ void __launch_bounds__(256, 2) k_gemm(const float* __restrict__ b_ker,
                                                 float* __restrict__ out) {
    extern __shared__ char smem[];
    float* sB    = (float*)(smem + SMEM_SB);
    float* sA    = (float*)(smem + SMEM_SA);
    float* sH[2] = { (float*)(smem + SMEM_H0), (float*)(smem + SMEM_H1) };
    int*   sCode = (int*)  (smem + SMEM_CODE);
    float* sFx   = (float*)(smem + SMEM_FX);
    float* sFy   = (float*)(smem + SMEM_FY);
    const U32 sB_u32 = (U32)__cvta_generic_to_shared(sB);
    const U32 sH_u32[2] = { (U32)__cvta_generic_to_shared(sH[0]),
                            (U32)__cvta_generic_to_shared(sH[1]) };

    const int tid = threadIdx.x;
    const int b  = blockIdx.z;
    const int h0 = blockIdx.y * 16, w0 = blockIdx.x * 8;
    const int warp = tid >> 5, lane = tid & 31;
    const int ty = ((warp & 1) << 3) | (lane >> 2);   // 0..15 pixel-group
    const int tx = ((warp >> 1) << 2) | (lane & 3);   // 0..15 cout-group
    const int pm  = tid & 127;                        // gather pixel
    const int chg = tid >> 7;                         // gather channel half

    // halo-fill constants for this thread (3 units of 16B per iteration)
    const float* xTb = g_xT + ((long)b << 19);
    int hsrc[3]; int hdst[3];
#pragma unroll
    for (int it = 0; it < 3; ++it) {
        int e = tid + (it << 8);          // 0..767
        int pos = e >> 1, g = e & 1;
        int hr = pos >> 4, wr = pos & 15;
        int gh = min(max(h0 - 4 + hr, 0), 63);
        int gw = min(max(w0 - 4 + wr, 0), 63);
        hsrc[it] = ((gh << 6) + gw) << 7;             // + chbase + g*4 later
        hdst[it] = ((hr * HPITCH + wr) * 8 + (g << 2)) * 4;
        hsrc[it] += (g << 2);
    }

    // ---- stage sampling meta once per block, keyed [n][pm]
    const float2* uvp = (const float2*)g_UV;
    for (int e = tid; e < 1152; e += 256) {
        int n = e >> 7, pp = e & 127;
        int h = h0 + (pp >> 3), w = w0 + (pp & 7);
        float2 uv = uvp[(b * 4096 + h * 64 + w) * 9 + n];
        float xf = floorf(uv.x), yf = floorf(uv.y);
        int ix = (int)xf, iy = (int)yf;
        int gcode = ix * 64 + iy;
        if (ix < 63) gcode |= (1 << 12);
        if (iy < 63) gcode |= (1 << 13);
        int hr = ix - (h0 - 4), wr = iy - (w0 - 4);
        int hcode = (hr * HPITCH + wr) & 4095;
        if (ix < 63) hcode |= (1 << 12);
        if (iy < 63) hcode |= (1 << 13);
        if (hr >= 0 && hr < 23 && wr >= 0 && wr < 15) hcode |= (1 << 14);
        sCode[e] = hcode | (gcode << 16);
        sFx[e] = uv.x - xf;
        sFy[e] = uv.y - yf;
    }

    ULL acc[8][4];
#pragma unroll
    for (int m = 0; m < 8; ++m)
#pragma unroll
        for (int j = 0; j < 4; ++j) acc[m][j] = pack2(0.f, 0.f);

    const int sa_base = (pm >> 3) * SA_GP + (pm & 7);

    // ---- prefetch halo(0)
#pragma unroll
    for (int it = 0; it < 3; ++it)
        cp_async16(sH_u32[0] + hdst[it], xTb + hsrc[it]);
    asm volatile("cp.async.commit_group;\n" ::: "memory");

    for (int cc = 0; cc < 16; ++cc) {
        const int chbase = cc * 8;
        const int buf = cc & 1;

        // ---- B tile: 72x128 = 2304 float4 via cp.async
        {
            const float* wsrc = g_Wt + cc * 72 * 128;
#pragma unroll
            for (int it = 0; it < 9; ++it) {
                int e = tid + (it << 8);
                cp_async16(sB_u32 + e * 16, wsrc + e * 4);
            }
            asm volatile("cp.async.commit_group;\n" ::: "memory");
        }
        // wait: halo(cc) + B(cc)
        asm volatile("cp.async.wait_group 0;\n" ::: "memory");
        __syncthreads();

        // ---- bilinear from halo smem; warp = 32 consecutive pm at fixed (n,chg)
        const float* hb = sH[buf];
#pragma unroll
        for (int n = 0; n < 9; ++n) {
            int p = (n << 7) + pm;
            float fx = sFx[p], fy = sFy[p];
            int code = sCode[p];
            float4 v00, v01, v10, v11;
            if (code & (1 << 14)) {
                const float* cb = hb + ((code & 4095) << 3) + (chg << 2);
                int dxs = (code & (1 << 12)) ? (HPITCH * 8) : 0;
                int dys = (code & (1 << 13)) ? 8 : 0;
                v00 = *(const float4*)(cb);
                v01 = *(const float4*)(cb + dys);
                v10 = *(const float4*)(cb + dxs);
                v11 = *(const float4*)(cb + dxs + dys);
            } else {
                int gc = code >> 16;
                const float* pb = xTb + ((long)(gc & 4095) << 7) + chbase + (chg << 2);
                int dxs = (gc & (1 << 12)) ? 8192 : 0;
                int dys = (gc & (1 << 13)) ? 128  : 0;
                v00 = *(const float4*)(pb);
                v01 = *(const float4*)(pb + dys);
                v10 = *(const float4*)(pb + dxs);
                v11 = *(const float4*)(pb + dxs + dys);
            }
            int ab = sa_base + (((chg << 2) * 9 + n) << 3);
            float r0, r1;
            r0 = v00.x + fy * (v01.x - v00.x);
            r1 = v10.x + fy * (v11.x - v10.x);
            sA[ab          ] = r0 + fx * (r1 - r0);
            r0 = v00.y + fy * (v01.y - v00.y);
            r1 = v10.y + fy * (v11.y - v10.y);
            sA[ab + 9 * 8  ] = r0 + fx * (r1 - r0);
            r0 = v00.z + fy * (v01.z - v00.z);
            r1 = v10.z + fy * (v11.z - v10.z);
            sA[ab + 18 * 8 ] = r0 + fx * (r1 - r0);
            r0 = v00.w + fy * (v01.w - v00.w);
            r1 = v10.w + fy * (v11.w - v10.w);
            sA[ab + 27 * 8 ] = r0 + fx * (r1 - r0);
        }
        __syncthreads();

        // ---- prefetch halo(cc+1) into the other buffer (lands during GEMM)
        if (cc < 15) {
            const int nchb = (cc + 1) * 8;
#pragma unroll
            for (int it = 0; it < 3; ++it)
                cp_async16(sH_u32[buf ^ 1] + hdst[it], xTb + hsrc[it] + nchb);
            asm volatile("cp.async.commit_group;\n" ::: "memory");
        }

        // ---- GEMM on the 72-deep chunk: 8M x 8N rank-1 updates
        const float* aRow = sA + ty * SA_GP;
#pragma unroll 8
        for (int kk = 0; kk < 72; ++kk) {
            float4 aL = *(const float4*)(aRow + (kk << 3));
            float4 aH = *(const float4*)(aRow + (kk << 3) + 4);
            ulonglong2 bl0 = *(const ulonglong2*)&sB[kk * 128 + (tx << 3)];
            ulonglong2 bl1 = *(const ulonglong2*)&sB[kk * 128 + (tx << 3) + 4];
            ULL a0 = pack2(aL.x, aL.x), a1 = pack2(aL.y, aL.y);
            ULL a2 = pack2(aL.z, aL.z), a3 = pack2(aL.w, aL.w);
            ULL a4 = pack2(aH.x, aH.x), a5 = pack2(aH.y, aH.y);
            ULL a6 = pack2(aH.z, aH.z), a7 = pack2(aH.w, aH.w);
            fma2(acc[0][0], a0, bl0.x); fma2(acc[0][1], a0, bl0.y);
            fma2(acc[0][2], a0, bl1.x); fma2(acc[0][3], a0, bl1.y);
            fma2(acc[1][0], a1, bl0.x); fma2(acc[1][1], a1, bl0.y);
            fma2(acc[1][2], a1, bl1.x); fma2(acc[1][3], a1, bl1.y);
            fma2(acc[2][0], a2, bl0.x); fma2(acc[2][1], a2, bl0.y);
            fma2(acc[2][2], a2, bl1.x); fma2(acc[2][3], a2, bl1.y);
            fma2(acc[3][0], a3, bl0.x); fma2(acc[3][1], a3, bl0.y);
            fma2(acc[3][2], a3, bl1.x); fma2(acc[3][3], a3, bl1.y);
            fma2(acc[4][0], a4, bl0.x); fma2(acc[4][1], a4, bl0.y);
            fma2(acc[4][2], a4, bl1.x); fma2(acc[4][3], a4, bl1.y);
            fma2(acc[5][0], a5, bl0.x); fma2(acc[5][1], a5, bl0.y);
            fma2(acc[5][2], a5, bl1.x); fma2(acc[5][3], a5, bl1.y);
            fma2(acc[6][0], a6, bl0.x); fma2(acc[6][1], a6, bl0.y);
            fma2(acc[6][2], a6, bl1.x); fma2(acc[6][3], a6, bl1.y);
            fma2(acc[7][0], a7, bl0.x); fma2(acc[7][1], a7, bl0.y);
            fma2(acc[7][2], a7, bl1.x); fma2(acc[7][3], a7, bl1.y);
        }
        __syncthreads();
    }

    // ---- epilogue: + bias.  Thread owns row h0+ty, w0..w0+7, couts tx*8+0..7.
    const int co0 = tx << 3;
    const int h = h0 + ty;
    float* op = out + (((long)(b * 128 + co0)) << 12) + (h << 6) + w0;
#pragma unroll
    for (int j = 0; j < 4; ++j) {
        float lo[8], hi[8];
#pragma unroll
        for (int m = 0; m < 8; ++m) unpack2(acc[m][j], lo[m], hi[m]);
        float bkl = b_ker[co0 + 2 * j];
        float bkh = b_ker[co0 + 2 * j + 1];
        float* o0 = op + ((long)(2 * j) << 12);
        float* o1 = op + ((long)(2 * j + 1) << 12);
        *(float4*)(o0)     = make_float4(lo[0] + bkl, lo[1] + bkl, lo[2] + bkl, lo[3] + bkl);
        *(float4*)(o0 + 4) = make_float4(lo[4] + bkl, lo[5] + bkl, lo[6] + bkl, lo[7] + bkl);
        *(float4*)(o1)     = make_float4(hi[0] + bkh, hi[1] + bkh, hi[2] + bkh, hi[3] + bkh);
        *(float4*)(o1 + 4) = make_float4(hi[4] + bkh, hi[5] + bkh, hi[6] + bkh, hi[7] + bkh);
    }
}

// ============================================================================
// launch
// ============================================================================
extern "C" void kernel_launch(void* const* d_in, const int* in_sizes, int n_in,
                              void* d_out, int out_size) {
    const float* x     = (const float*)d_in[0];
    const float* w_off = (const float*)d_in[1];
    const float* b_off = (const float*)d_in[2];
    const float* w_ker = (const float*)d_in[3];
    const float* b_ker = (const float*)d_in[4];
    float* out = (float*)d_out;

    cudaFuncSetAttribute(k_gemm, cudaFuncAttributeMaxDynamicSharedMemorySize,
                         SMEM_TOT);

    k_wt<<<(1152 * 128 + 255) / 256, 256, 0, 0>>>(w_ker);
    k_tr<<<dim3(128, 4, 8), dim3(32, 8), 0, 0>>>(x);
    k_offset<<<dim3(4, 4, 8), 512, 0, 0>>>(x, w_off, b_off);
    k_gemm<<<dim3(8, 4, 8), 256, SMEM_TOT, 0>>>(b_ker, out);
}